// round 9
// baseline (speedup 1.0000x reference)
#include <cuda_runtime.h>
#include <cuda_bf16.h>
#include <cstdint>

#define NPTS   64
#define NANGS  2016
#define NCOLS  300000
#define NSEG   8
#define LSEG   (NANGS / NSEG)   // 252

typedef unsigned int u32;

__device__ float g_M[NSEG * NPTS * NPTS];
__device__ float g_P[(NSEG/2) * NPTS * NPTS];
__device__ float g_Q[(NSEG/4) * NPTS * NPTS];
__device__ float g_R[NPTS * NPTS];

__device__ __forceinline__ u32 smem_u32(const void* p) {
    u32 a;
    asm("{ .reg .u64 t; cvta.to.shared.u64 t, %1; cvt.u32.u64 %0, t; }"
        : "=r"(a) : "l"(p));
    return a;
}

// ---------------------------------------------------------------------------
// Kernel 1: 8 parallel segment matrices (R5 structure, proven fast).
// ---------------------------------------------------------------------------
__global__ void __launch_bounds__(NPTS, 1)
build_seg_kernel(const float* __restrict__ angles) {
    __shared__ float2 cs[LSEG];
    __shared__ float  Rs[NPTS * NPTS];

    const int j  = threadIdx.x;
    const int i0 = blockIdx.x * LSEG;
    const int i1 = i0 + LSEG;

    for (int i = j; i < LSEG; i += NPTS) {
        float sv, cv;
        __sincosf(angles[i0 + i], &sv, &cv);
        cs[i] = make_float2(cv, sv);
    }
    for (int r = 0; r < NPTS; r++) Rs[r * NPTS + j] = (r == j) ? 1.0f : 0.0f;
    __syncthreads();

#pragma unroll 1
    for (int t = 0; t < NPTS - 1; t++) {
        const int gs   = t * (2 * NPTS - 1 - t) / 2;
        const int glen = NPTS - 1 - t;
        if (gs >= i1) break;
        if (gs + glen <= i0) continue;
        int lo = i0 - gs; if (lo < 0) lo = 0;
        int hi = i1 - gs; if (hi > glen) hi = glen;

        float rt = Rs[t * NPTS + j];
#pragma unroll 7
        for (int b = t + 1 + lo; b < t + 1 + hi; b++) {
            const float2 p  = cs[gs + (b - t - 1) - i0];
            const float  rb = Rs[b * NPTS + j];
            Rs[b * NPTS + j] = fmaf(p.y, rt, p.x * rb);
            rt = fmaf(p.x, rt, -(p.y * rb));
        }
        Rs[t * NPTS + j] = rt;
    }

    float* M = g_M + blockIdx.x * (NPTS * NPTS);
    for (int r = 0; r < NPTS; r++) M[r * NPTS + j] = Rs[r * NPTS + j];
}

// ---------------------------------------------------------------------------
// Kernel 2 (x3 levels): pairwise 64x64 products, 2 blocks per product.
// ---------------------------------------------------------------------------
__global__ void __launch_bounds__(256, 1)
matprod_kernel(int level, const float* __restrict__ mus) {
    __shared__ float As[NPTS * NPTS];   // column-major: As[k*64 + r]
    __shared__ float Bs[NPTS * 32];

    const float* in  = (level == 0) ? g_M : (level == 1) ? g_P : g_Q;
    float*       out = (level == 0) ? g_P : (level == 1) ? g_Q : g_R;
    const int use_mus = (level == 2);

    const int p = blockIdx.x >> 1;
    const int h = blockIdx.x & 1;
    const float* A = in + (2 * p + 1) * (NPTS * NPTS);
    const float* B = in + (2 * p) * (NPTS * NPTS) + h * 32;
    float*       C = out + p * (NPTS * NPTS) + h * 32;

    for (int idx = threadIdx.x; idx < NPTS * NPTS; idx += 256) {
        const int k = idx >> 6, r = idx & 63;
        As[k * NPTS + r] = A[r * NPTS + k];
    }
    for (int idx = threadIdx.x; idx < NPTS * 32; idx += 256) {
        const int k = idx >> 5, jl = idx & 31;
        Bs[idx] = B[k * NPTS + jl];
    }
    __syncthreads();

    const int jl = threadIdx.x & 31;
    const int rq = threadIdx.x >> 5;

    float acc[8];
#pragma unroll
    for (int i = 0; i < 8; i++) acc[i] = 0.0f;

#pragma unroll 8
    for (int k = 0; k < NPTS; k++) {
        const float  b  = Bs[k * 32 + jl];
        const float4 a0 = *reinterpret_cast<const float4*>(&As[k * NPTS + rq * 8]);
        const float4 a1 = *reinterpret_cast<const float4*>(&As[k * NPTS + rq * 8 + 4]);
        acc[0] = fmaf(a0.x, b, acc[0]);
        acc[1] = fmaf(a0.y, b, acc[1]);
        acc[2] = fmaf(a0.z, b, acc[2]);
        acc[3] = fmaf(a0.w, b, acc[3]);
        acc[4] = fmaf(a1.x, b, acc[4]);
        acc[5] = fmaf(a1.y, b, acc[5]);
        acc[6] = fmaf(a1.z, b, acc[6]);
        acc[7] = fmaf(a1.w, b, acc[7]);
    }

#pragma unroll
    for (int i = 0; i < 8; i++) {
        const int r = rq * 8 + i;
        float v = acc[i];
        if (use_mus) v *= mus[r];
        C[r * NPTS + jl] = v;
    }
}

// ---------------------------------------------------------------------------
// Kernel 3: Y = R @ X via bf16 split HMMA (3-term), ILP-restructured:
//  - all 8 ldmatrix.x4 per k-step hoisted up-front (latency hidden by cvts)
//  - 24 MMAs issued in 3 rounds of 8 INDEPENDENT accumulator chains
// ---------------------------------------------------------------------------
#define LDR 36

#define CVT_PACK(d, x1, x0) \
    asm("cvt.rn.bf16x2.f32 %0, %1, %2;" : "=r"(d) : "f"(x1), "f"(x0))

#define LDMX4(FR, ADDR)                                                        \
    asm volatile("ldmatrix.sync.aligned.m8n8.x4.shared.b16 {%0,%1,%2,%3}, [%4];" \
                 : "=r"(FR[0]), "=r"(FR[1]), "=r"(FR[2]), "=r"(FR[3]) : "r"(ADDR))

#define MMA_BF16(ACC, A, B0, B1)                                               \
    asm volatile(                                                              \
        "mma.sync.aligned.m16n8k16.row.col.f32.bf16.bf16.f32 "                 \
        "{%0,%1,%2,%3},{%4,%5,%6,%7},{%8,%9},{%0,%1,%2,%3};"                   \
        : "+f"(ACC[0]), "+f"(ACC[1]), "+f"(ACC[2]), "+f"(ACC[3])               \
        : "r"(A[0]), "r"(A[1]), "r"(A[2]), "r"(A[3]), "r"(B0), "r"(B1))

__global__ void __launch_bounds__(256, 2)
gemm_hmma_kernel(const float* __restrict__ X, float* __restrict__ Y) {
    __shared__ u32 RhiS[NPTS * LDR];
    __shared__ u32 RloS[NPTS * LDR];

    for (int idx = threadIdx.x; idx < NPTS * 32; idx += 256) {
        const int row = idx >> 5, kp = idx & 31;
        const float x0 = g_R[row * NPTS + 2 * kp];
        const float x1 = g_R[row * NPTS + 2 * kp + 1];
        u32 hh; CVT_PACK(hh, x1, x0);
        const float h0 = __uint_as_float(hh << 16);
        const float h1 = __uint_as_float(hh & 0xFFFF0000u);
        u32 ll; CVT_PACK(ll, x1 - h1, x0 - h0);
        RhiS[row * LDR + kp] = hh;
        RloS[row * LDR + kp] = ll;
    }
    __syncthreads();

    const int warp = threadIdx.x >> 5;
    const int lane = threadIdx.x & 31;
    const int g = lane >> 2;
    const int t = lane & 3;

    const long n0 = (long)blockIdx.x * 128 + warp * 16;
    if (n0 + 16 > NCOLS) return;

    const int r8   = lane & 7;
    const int selm = (lane >> 3) & 1;
    const int selk = (lane >> 4) & 1;
    const u32 laneoff = (u32)(((selm * 8 + r8) * LDR + selk * 4) * 4);
    const u32 ahibase = smem_u32(RhiS) + laneoff;
    const u32 alobase = smem_u32(RloS) + laneoff;

    float acc[4][2][4];
#pragma unroll
    for (int mt = 0; mt < 4; mt++)
#pragma unroll
        for (int nt = 0; nt < 2; nt++)
#pragma unroll
            for (int q = 0; q < 4; q++) acc[mt][nt][q] = 0.0f;

    const float* __restrict__ xb = X + n0 + g;
    float raw[2][8];

#define LOADK(BUF, KS)                                                         \
    do {                                                                       \
        const size_t o  = (size_t)((KS)*16 + 2 * t) * NCOLS;                   \
        const size_t o8 = o + (size_t)8 * NCOLS;                               \
        raw[BUF][0] = xb[o];      raw[BUF][1] = xb[o + NCOLS];                 \
        raw[BUF][2] = xb[o8];     raw[BUF][3] = xb[o8 + NCOLS];                \
        raw[BUF][4] = xb[o + 8];  raw[BUF][5] = xb[o + NCOLS + 8];             \
        raw[BUF][6] = xb[o8 + 8]; raw[BUF][7] = xb[o8 + NCOLS + 8];            \
    } while (0)

    LOADK(0, 0);
    LOADK(1, 1);

#pragma unroll
    for (int ks = 0; ks < 4; ks++) {
        const int cur = ks & 1;

        // ---- hoist ALL A-fragment loads for this k-step (8x ldmatrix.x4) ----
        u32 fh[4][4], fl[4][4];
#pragma unroll
        for (int mt = 0; mt < 4; mt++) {
            const u32 off = (u32)(mt * 16 * LDR * 4 + ks * 32);
            LDMX4(fh[mt], ahibase + off);
            LDMX4(fl[mt], alobase + off);
        }

        // ---- bf16 hi/lo split of X (independent; fills LDSM latency) ----
        u32 bhi[2][2], blo[2][2];
#pragma unroll
        for (int nt = 0; nt < 2; nt++) {
#pragma unroll
            for (int h2 = 0; h2 < 2; h2++) {
                const float x0 = raw[cur][nt * 4 + h2 * 2];
                const float x1 = raw[cur][nt * 4 + h2 * 2 + 1];
                u32 hh; CVT_PACK(hh, x1, x0);
                const float h0 = __uint_as_float(hh << 16);
                const float h1 = __uint_as_float(hh & 0xFFFF0000u);
                u32 ll; CVT_PACK(ll, x1 - h1, x0 - h0);
                bhi[nt][h2] = hh;
                blo[nt][h2] = ll;
            }
        }

        if (ks + 2 < 4) LOADK(cur, ks + 2);

        // ---- 3 rounds of 8 independent MMA chains ----
#pragma unroll
        for (int mt = 0; mt < 4; mt++)
#pragma unroll
            for (int nt = 0; nt < 2; nt++)
                MMA_BF16(acc[mt][nt], fh[mt], bhi[nt][0], bhi[nt][1]);
#pragma unroll
        for (int mt = 0; mt < 4; mt++)
#pragma unroll
            for (int nt = 0; nt < 2; nt++)
                MMA_BF16(acc[mt][nt], fh[mt], blo[nt][0], blo[nt][1]);
#pragma unroll
        for (int mt = 0; mt < 4; mt++)
#pragma unroll
            for (int nt = 0; nt < 2; nt++)
                MMA_BF16(acc[mt][nt], fl[mt], bhi[nt][0], bhi[nt][1]);
    }
#undef LOADK

#pragma unroll
    for (int mt = 0; mt < 4; mt++) {
        const int r0 = mt * 16 + g;
#pragma unroll
        for (int nt = 0; nt < 2; nt++) {
            const long col = n0 + 8 * nt + 2 * t;
            *reinterpret_cast<float2*>(Y + (size_t)r0 * NCOLS + col) =
                make_float2(acc[mt][nt][0], acc[mt][nt][1]);
            *reinterpret_cast<float2*>(Y + (size_t)(r0 + 8) * NCOLS + col) =
                make_float2(acc[mt][nt][2], acc[mt][nt][3]);
        }
    }
}

// ---------------------------------------------------------------------------
// Inputs (metadata order): X (64*300000 f32), angles (2016 f32), mus (64 f32).
// ---------------------------------------------------------------------------
extern "C" void kernel_launch(void* const* d_in, const int* in_sizes, int n_in,
                              void* d_out, int out_size) {
    const float* X      = (const float*)d_in[0];
    const float* angles = (const float*)d_in[1];
    const float* mus    = (const float*)d_in[2];
    float* Y            = (float*)d_out;

    build_seg_kernel<<<NSEG, NPTS>>>(angles);
    matprod_kernel<<<NSEG, 256>>>(0, mus);
    matprod_kernel<<<NSEG / 2, 256>>>(1, mus);
    matprod_kernel<<<NSEG / 4, 256>>>(2, mus);

    const int blocks = (NCOLS + 127) / 128;   // 2344
    gemm_hmma_kernel<<<blocks, 256>>>(X, Y);
}